// round 4
// baseline (speedup 1.0000x reference)
#include <cuda_runtime.h>
#include <cstdint>
#include <math.h>

#define B_  64
#define T_  512
#define N_  128
#define H_  512
#define G_  2048              // 4*H
#define BT_ (B_ * T_)         // 32768
#define NBLK 128              // persistent scan blocks (1/SM, all co-resident)

typedef unsigned long long ull;

// packed f32x2 helpers
#define FMA2(d, a, b, c) asm("fma.rn.f32x2 %0, %1, %2, %3;" : "=l"(d) : "l"(a), "l"(b), "l"(c))
#define PACK2(d, lo, hi) asm("mov.b64 %0, {%1, %2};" : "=l"(d) : "f"(lo), "f"(hi))
#define UNPACK2(lo, hi, v) asm("mov.b64 {%0, %1}, %2;" : "=f"(lo), "=f"(hi) : "l"(v))

// cp.async helpers
#define CP_ASYNC16(dst_smem_u32, src_gmem_ptr) \
    asm volatile("cp.async.cg.shared.global [%0], [%1], 16;" :: "r"(dst_smem_u32), "l"(src_gmem_ptr) : "memory")
#define CP_COMMIT() asm volatile("cp.async.commit_group;" ::: "memory")
#define CP_WAIT(n)  asm volatile("cp.async.wait_group %0;" :: "n"(n) : "memory")

// -------- device scratch (allocation-free rule: __device__ globals) --------
__device__ float g_xg[(size_t)BT_ * G_];   // 268 MB: X@Wx + b, [bt][4H]
__device__ float g_hs[(size_t)BT_ * H_];   // 67 MB: h history [b][t][H] (for out_loss)
__device__ float g_hT[H_ * B_];            // 128 KB: current h, k-major [u][b] (scan-internal)
__device__ float g_lpart[2048];            // per-block loss partials
__device__ unsigned g_bar_count;
__device__ volatile unsigned g_bar_gen;

// -------- software grid barrier (all NBLK blocks resident), plain spin --------
__device__ __forceinline__ void grid_barrier(unsigned nblocks) {
    __threadfence();
    __syncthreads();
    if (threadIdx.x == 0) {
        unsigned gen = g_bar_gen;
        unsigned a = atomicAdd(&g_bar_count, 1u);
        if (a == nblocks - 1) {
            g_bar_count = 0;
            __threadfence();
            g_bar_gen = gen + 1;
        } else {
            while (g_bar_gen == gen) { }
        }
    }
    __syncthreads();
}

// ============================================================
// Kernel A: xg = X @ Wx + b   (M=32768, K=128, N=2048), f32x2 packed
// 64x64 tile, 256 threads; thread = 4 rows x 4 cols.
// Xst: transposed X tile (row-pairs free via ulonglong2).
// Wsd: duplicated weights (w,w) so FFMA2 needs zero packs.
// ============================================================
__global__ void __launch_bounds__(256) xg_gemm(
    const float* __restrict__ X, const float* __restrict__ Wx,
    const float* __restrict__ bias)
{
    __shared__ float Xst[64 * 68];    // [k][row], pad 68 (16B-aligned rows)
    __shared__ float Wsd[64 * 128];   // [k][col-dup]: (w0,w0,w1,w1,...)
    int tid = threadIdx.x;
    int m0 = blockIdx.y * 64;
    int n0 = blockIdx.x * 64;
    int cx = tid & 15, ry = tid >> 4;
    int c8 = cx * 8;

    ull acc[2][4] = {};    // [row-pair][col]; f32x2 zero == 0ull

    for (int kc = 0; kc < 128; kc += 64) {
        __syncthreads();
        #pragma unroll
        for (int i = 0; i < 16; i++) {
            int idx = tid + i * 256;          // 0..4095
            int k = idx & 63, r = idx >> 6;
            Xst[k * 68 + r] = X[(size_t)(m0 + r) * 128 + kc + k];
        }
        #pragma unroll
        for (int i = 0; i < 32; i++) {
            int idx = tid + i * 256;          // 0..8191
            int k = idx >> 7, rem = idx & 127;
            Wsd[k * 128 + rem] = Wx[(size_t)(kc + k) * G_ + n0 + (rem >> 1)];
        }
        __syncthreads();
        #pragma unroll 8
        for (int k = 0; k < 64; k++) {
            ulonglong2 hq  = *(const ulonglong2*)&Xst[k * 68 + ry * 4];     // (r0,r1),(r2,r3)
            ulonglong2 wq0 = *(const ulonglong2*)&Wsd[k * 128 + c8];        // (c0c0),(c1c1)
            ulonglong2 wq1 = *(const ulonglong2*)&Wsd[k * 128 + c8 + 4];    // (c2c2),(c3c3)
            FMA2(acc[0][0], hq.x, wq0.x, acc[0][0]);
            FMA2(acc[0][1], hq.x, wq0.y, acc[0][1]);
            FMA2(acc[0][2], hq.x, wq1.x, acc[0][2]);
            FMA2(acc[0][3], hq.x, wq1.y, acc[0][3]);
            FMA2(acc[1][0], hq.y, wq0.x, acc[1][0]);
            FMA2(acc[1][1], hq.y, wq0.y, acc[1][1]);
            FMA2(acc[1][2], hq.y, wq1.x, acc[1][2]);
            FMA2(acc[1][3], hq.y, wq1.y, acc[1][3]);
        }
    }
    float4 bb = *(const float4*)&bias[n0 + cx * 4];
    #pragma unroll
    for (int j = 0; j < 2; j++) {
        float lo[4], hi[4];
        #pragma unroll
        for (int cp = 0; cp < 4; cp++) UNPACK2(lo[cp], hi[cp], acc[j][cp]);
        int row0 = m0 + ry * 4 + j * 2;
        *(float4*)&g_xg[(size_t)row0 * G_ + n0 + cx * 4] =
            make_float4(lo[0] + bb.x, lo[1] + bb.y, lo[2] + bb.z, lo[3] + bb.w);
        *(float4*)&g_xg[(size_t)(row0 + 1) * G_ + n0 + cx * 4] =
            make_float4(hi[0] + bb.x, hi[1] + bb.y, hi[2] + bb.z, hi[3] + bb.w);
    }
}

// ============================================================
// Kernel B: persistent LSTM scan, ONE grid barrier per step.
// Block bid owns 4 hidden units (all 4 gates = 16 gate-cols), full K=512.
//   smem: h_s [512 k][64 b] (128 KB) + Wh_d duplicated [128 kc][16 c][8] (64 KB)
//   h pipelined in 4 chunks via cp.async from g_hT (k-major mirror).
//   Phase 2 is block-local: 1 cell/thread, c in register.
// ============================================================
#define SMEM_SCAN ((H_ * B_ + 128 * 16 * 8) * 4)   // 131072 + 65536 = 196608 B

__global__ void __launch_bounds__(256, 1) lstm_scan(const float* __restrict__ Wh)
{
    extern __shared__ float smem[];
    float* h_s    = smem;                 // [512][64]
    float* Wh_d   = smem + H_ * B_;       // [128 kc][16 c][8] duplicated (w,w)
    float* gate_s = smem;                 // reuse of h_s head after phase 1

    int tid = threadIdx.x;
    int bid = blockIdx.x;
    int u0 = bid * 4;                     // this block's 4 hidden units

    // build duplicated Wh slice once (persists all 512 steps)
    #pragma unroll
    for (int i = 0; i < 64; i++) {
        int idx = tid + i * 256;          // 0..16383
        int kc = idx >> 7, rem = idx & 127;
        int c = rem >> 3, j = rem & 7, r = j >> 1;
        int gi = c >> 2, ul2 = c & 3;
        Wh_d[idx] = Wh[(size_t)(kc * 4 + r) * G_ + gi * 512 + u0 + ul2];
    }

    // phase-1 thread coords: c = gate-col (0..15), bg = batch group (0..15)
    int c  = tid & 15, bg = tid >> 4;
    int c8 = c * 8, bg4 = bg * 4;
    // phase-2 thread coords: one cell
    int b_cell = tid >> 2;                // batch 0..63
    int ul     = tid & 3;                 // unit-local 0..3
    int u_cell = u0 + ul;
    float creg = 0.0f;

    uint32_t hs_base = (uint32_t)__cvta_generic_to_shared(h_s);

    for (int t = 0; t < T_; t++) {
        // prefetch xg for this step's phase-2 (independent of barrier)
        float xgv[4];
        {
            size_t xoff = ((size_t)(b_cell * T_ + t)) * G_;
            #pragma unroll
            for (int gi = 0; gi < 4; gi++)
                xgv[gi] = g_xg[xoff + gi * 512 + u_cell];
        }

        ull acc01 = 0ull, acc23 = 0ull;   // (b0,b1) and (b2,b3) for this thread's col

        auto compute_chunk = [&](int ch) {
            #pragma unroll 4
            for (int kc4 = 0; kc4 < 32; kc4++) {
                int kc = (ch << 5) + kc4;
                ulonglong2 wq0 = *(const ulonglong2*)&Wh_d[kc * 128 + c8];       // r0,r1 dup
                ulonglong2 wq1 = *(const ulonglong2*)&Wh_d[kc * 128 + c8 + 4];   // r2,r3 dup
                ulonglong2 h0 = *(const ulonglong2*)&h_s[(kc * 4 + 0) * 64 + bg4];
                FMA2(acc01, h0.x, wq0.x, acc01);
                FMA2(acc23, h0.y, wq0.x, acc23);
                ulonglong2 h1 = *(const ulonglong2*)&h_s[(kc * 4 + 1) * 64 + bg4];
                FMA2(acc01, h1.x, wq0.y, acc01);
                FMA2(acc23, h1.y, wq0.y, acc23);
                ulonglong2 h2 = *(const ulonglong2*)&h_s[(kc * 4 + 2) * 64 + bg4];
                FMA2(acc01, h2.x, wq1.x, acc01);
                FMA2(acc23, h2.y, wq1.x, acc23);
                ulonglong2 h3 = *(const ulonglong2*)&h_s[(kc * 4 + 3) * 64 + bg4];
                FMA2(acc01, h3.x, wq1.y, acc01);
                FMA2(acc23, h3.y, wq1.y, acc23);
            }
        };

        if (t == 0) {
            // zero h(−1)
            #pragma unroll
            for (int i = 0; i < 32; i++)
                *(float4*)&h_s[(tid + i * 256) * 4] = make_float4(0.f, 0.f, 0.f, 0.f);
            __syncthreads();
            compute_chunk(0); compute_chunk(1); compute_chunk(2); compute_chunk(3);
        } else {
            // pipelined h load: 4 chunks of 32 KB each, cp.async overlapped
            #pragma unroll
            for (int i = 0; i < 8; i++) {
                int idx = tid + i * 256;                 // float4 index within chunk 0
                CP_ASYNC16(hs_base + idx * 16, (const void*)&g_hT[idx * 4]);
            }
            CP_COMMIT();
            #pragma unroll
            for (int ch = 0; ch < 4; ch++) {
                if (ch < 3) {
                    int base = (ch + 1) * 2048;          // float4 offset of next chunk
                    #pragma unroll
                    for (int i = 0; i < 8; i++) {
                        int idx = base + tid + i * 256;
                        CP_ASYNC16(hs_base + idx * 16, (const void*)&g_hT[idx * 4]);
                    }
                    CP_COMMIT();
                    CP_WAIT(1);
                } else {
                    CP_WAIT(0);
                }
                __syncthreads();
                compute_chunk(ch);
            }
        }

        // phase-1 -> smem transpose buffer (gate_s rows padded to 68)
        __syncthreads();
        {
            float a0, a1, a2, a3;
            UNPACK2(a0, a1, acc01);
            UNPACK2(a2, a3, acc23);
            *(float4*)&gate_s[c * 68 + bg4] = make_float4(a0, a1, a2, a3);
        }
        __syncthreads();

        // phase 2: one cell per thread
        {
            float s0 = gate_s[(0 * 4 + ul) * 68 + b_cell] + xgv[0];   // i
            float s1 = gate_s[(1 * 4 + ul) * 68 + b_cell] + xgv[1];   // j
            float s2 = gate_s[(2 * 4 + ul) * 68 + b_cell] + xgv[2];   // f
            float s3 = gate_s[(3 * 4 + ul) * 68 + b_cell] + xgv[3];   // o
            float ig = 1.0f / (1.0f + expf(-s0));
            float jg = tanhf(s1);
            float fg = 1.0f / (1.0f + expf(-(s2 + 1.0f)));            // forget_bias=1
            float og = 1.0f / (1.0f + expf(-s3));
            creg = fg * creg + ig * jg;
            float h = og * tanhf(creg);
            g_hT[u_cell * 64 + b_cell] = h;                           // k-major mirror for next step
            g_hs[((size_t)(b_cell * T_ + t)) * H_ + u_cell] = h;      // history for out_loss
        }
        grid_barrier(NBLK);
    }
}

// ============================================================
// Kernel C: logits = sigmoid(hs@Wd + bd); per-block partial MSE (f32x2 packed)
// block = 16 bt-rows x 128 cols; 256 threads; thread = 8 rows x 1 col
// ============================================================
__global__ void __launch_bounds__(256) out_loss(
    const float* __restrict__ Wd, const float* __restrict__ bd,
    const float* __restrict__ Y)
{
    __shared__ float h_s[512 * 20];   // [k][r] padded
    __shared__ float red[8];
    int tid = threadIdx.x;
    int row0 = blockIdx.x * 16;

    #pragma unroll
    for (int i = 0; i < 32; i++) {
        int idx = tid + i * 256;             // 0..8191
        int r = idx >> 9, k = idx & 511;
        h_s[k * 20 + r] = g_hs[(size_t)(row0 + r) * H_ + k];
    }
    __syncthreads();

    int cc = tid & 127;
    int rh = tid >> 7;                       // 0..1 -> rows rh*8..+7
    ull acc2[4] = {};
    #pragma unroll 4
    for (int k = 0; k < 512; k++) {
        float w = Wd[(size_t)k * N_ + cc];
        ull wd; PACK2(wd, w, w);
        ulonglong2 ha = *(const ulonglong2*)&h_s[k * 20 + rh * 8];
        ulonglong2 hb = *(const ulonglong2*)&h_s[k * 20 + rh * 8 + 4];
        FMA2(acc2[0], ha.x, wd, acc2[0]);
        FMA2(acc2[1], ha.y, wd, acc2[1]);
        FMA2(acc2[2], hb.x, wd, acc2[2]);
        FMA2(acc2[3], hb.y, wd, acc2[3]);
    }
    float accv[8];
    #pragma unroll
    for (int p = 0; p < 4; p++) UNPACK2(accv[2 * p], accv[2 * p + 1], acc2[p]);

    float bdc = bd[cc];
    float lsum = 0.0f;
    #pragma unroll
    for (int i = 0; i < 8; i++) {
        int row = row0 + rh * 8 + i;
        float logit = 1.0f / (1.0f + expf(-(accv[i] + bdc)));
        float d = Y[(size_t)row * N_ + cc] - logit;
        lsum += d * d;
    }
    #pragma unroll
    for (int o = 16; o; o >>= 1) lsum += __shfl_xor_sync(0xFFFFFFFFu, lsum, o);
    if ((tid & 31) == 0) red[tid >> 5] = lsum;
    __syncthreads();
    if (tid == 0) {
        float s = 0.0f;
        #pragma unroll
        for (int i = 0; i < 8; i++) s += red[i];
        g_lpart[blockIdx.x] = s;
    }
}

// ============================================================
// Kernel D: final deterministic reduction -> loss scalar
// ============================================================
__global__ void finalize(float* __restrict__ out)
{
    __shared__ float red[8];
    int tid = threadIdx.x;
    float s = 0.0f;
    for (int i = tid; i < 2048; i += 256) s += g_lpart[i];
    #pragma unroll
    for (int o = 16; o; o >>= 1) s += __shfl_xor_sync(0xFFFFFFFFu, s, o);
    if ((tid & 31) == 0) red[tid >> 5] = s;
    __syncthreads();
    if (tid == 0) {
        float t = 0.0f;
        #pragma unroll
        for (int i = 0; i < 8; i++) t += red[i];
        out[0] = t * (100.0f / ((float)B_ * (float)T_ * (float)N_));
    }
}

// ============================================================
extern "C" void kernel_launch(void* const* d_in, const int* in_sizes, int n_in,
                              void* d_out, int out_size)
{
    const float* X  = (const float*)d_in[0];
    const float* Y  = (const float*)d_in[1];
    const float* Wx = (const float*)d_in[2];
    const float* Wh = (const float*)d_in[3];
    const float* b  = (const float*)d_in[4];
    const float* Wd = (const float*)d_in[5];
    const float* bd = (const float*)d_in[6];
    (void)in_sizes; (void)n_in; (void)out_size;

    cudaFuncSetAttribute(lstm_scan, cudaFuncAttributeMaxDynamicSharedMemorySize, SMEM_SCAN);

    dim3 gA(G_ / 64, BT_ / 64);                 // 32 x 512
    xg_gemm<<<gA, 256>>>(X, Wx, b);
    lstm_scan<<<NBLK, 256, SMEM_SCAN>>>(Wh);
    out_loss<<<BT_ / 16, 256>>>(Wd, bd, Y);     // 2048 blocks
    finalize<<<1, 256>>>((float*)d_out);
}

// round 5
// speedup vs baseline: 1.1836x; 1.1836x over previous
#include <cuda_runtime.h>
#include <cstdint>
#include <math.h>

#define B_  64
#define T_  512
#define N_  128
#define H_  512
#define G_  2048              // 4*H
#define BT_ (B_ * T_)         // 32768
#define NBLK 128              // persistent scan blocks (1/SM, all co-resident)

typedef unsigned long long ull;

// packed f32x2 helpers
#define FMA2(d, a, b, c) asm("fma.rn.f32x2 %0, %1, %2, %3;" : "=l"(d) : "l"(a), "l"(b), "l"(c))
#define PACK2(d, lo, hi) asm("mov.b64 %0, {%1, %2};" : "=l"(d) : "f"(lo), "f"(hi))
#define UNPACK2(lo, hi, v) asm("mov.b64 {%0, %1}, %2;" : "=f"(lo), "=f"(hi) : "l"(v))

// cp.async helpers (.cg = L1-bypass, L2-direct: also gives cross-SM visibility)
#define CP_ASYNC16(dst_smem_u32, src_gmem_ptr) \
    asm volatile("cp.async.cg.shared.global [%0], [%1], 16;" :: "r"(dst_smem_u32), "l"(src_gmem_ptr) : "memory")
#define CP_COMMIT() asm volatile("cp.async.commit_group;" ::: "memory")
#define CP_WAIT(n)  asm volatile("cp.async.wait_group %0;" :: "n"(n) : "memory")

// -------- device scratch (allocation-free rule: __device__ globals) --------
__device__ float g_xg[(size_t)BT_ * G_];   // 268 MB: X@Wx + b, [bt][4H]
__device__ float g_hs[(size_t)BT_ * H_];   // 67 MB: h history [b][t][H] (for out_loss)
__device__ float g_hTd[H_ * 2 * B_];       // 256 KB: current h, duplicated [u][(h_b,h_b) x 64]
__device__ float g_lpart[2048];            // per-block loss partials
__device__ unsigned g_bar_count;
__device__ volatile unsigned g_bar_gen;

// -------- software grid barrier (all NBLK blocks resident), plain spin --------
__device__ __forceinline__ void grid_barrier(unsigned nblocks) {
    __threadfence();
    __syncthreads();
    if (threadIdx.x == 0) {
        unsigned gen = g_bar_gen;
        unsigned a = atomicAdd(&g_bar_count, 1u);
        if (a == nblocks - 1) {
            g_bar_count = 0;
            __threadfence();
            g_bar_gen = gen + 1;
        } else {
            while (g_bar_gen == gen) { }
        }
    }
    __syncthreads();
}

// ============================================================
// Kernel A: xg = X @ Wx + b   (M=32768, K=128, N=2048), f32x2 packed
// ============================================================
__global__ void __launch_bounds__(256) xg_gemm(
    const float* __restrict__ X, const float* __restrict__ Wx,
    const float* __restrict__ bias)
{
    __shared__ float Xst[64 * 68];    // [k][row], transposed X tile
    __shared__ float Wsd[64 * 128];   // [k][col-dup]: (w0,w0,w1,w1,...)
    int tid = threadIdx.x;
    int m0 = blockIdx.y * 64;
    int n0 = blockIdx.x * 64;
    int cx = tid & 15, ry = tid >> 4;
    int c8 = cx * 8;

    ull acc[2][4] = {};

    for (int kc = 0; kc < 128; kc += 64) {
        __syncthreads();
        #pragma unroll
        for (int i = 0; i < 16; i++) {
            int idx = tid + i * 256;
            int k = idx & 63, r = idx >> 6;
            Xst[k * 68 + r] = X[(size_t)(m0 + r) * 128 + kc + k];
        }
        #pragma unroll
        for (int i = 0; i < 32; i++) {
            int idx = tid + i * 256;
            int k = idx >> 7, rem = idx & 127;
            Wsd[k * 128 + rem] = Wx[(size_t)(kc + k) * G_ + n0 + (rem >> 1)];
        }
        __syncthreads();
        #pragma unroll 8
        for (int k = 0; k < 64; k++) {
            ulonglong2 hq  = *(const ulonglong2*)&Xst[k * 68 + ry * 4];
            ulonglong2 wq0 = *(const ulonglong2*)&Wsd[k * 128 + c8];
            ulonglong2 wq1 = *(const ulonglong2*)&Wsd[k * 128 + c8 + 4];
            FMA2(acc[0][0], hq.x, wq0.x, acc[0][0]);
            FMA2(acc[0][1], hq.x, wq0.y, acc[0][1]);
            FMA2(acc[0][2], hq.x, wq1.x, acc[0][2]);
            FMA2(acc[0][3], hq.x, wq1.y, acc[0][3]);
            FMA2(acc[1][0], hq.y, wq0.x, acc[1][0]);
            FMA2(acc[1][1], hq.y, wq0.y, acc[1][1]);
            FMA2(acc[1][2], hq.y, wq1.x, acc[1][2]);
            FMA2(acc[1][3], hq.y, wq1.y, acc[1][3]);
        }
    }
    float4 bb = *(const float4*)&bias[n0 + cx * 4];
    #pragma unroll
    for (int j = 0; j < 2; j++) {
        float lo[4], hi[4];
        #pragma unroll
        for (int cp = 0; cp < 4; cp++) UNPACK2(lo[cp], hi[cp], acc[j][cp]);
        int row0 = m0 + ry * 4 + j * 2;
        *(float4*)&g_xg[(size_t)row0 * G_ + n0 + cx * 4] =
            make_float4(lo[0] + bb.x, lo[1] + bb.y, lo[2] + bb.z, lo[3] + bb.w);
        *(float4*)&g_xg[(size_t)(row0 + 1) * G_ + n0 + cx * 4] =
            make_float4(hi[0] + bb.x, hi[1] + bb.y, hi[2] + bb.z, hi[3] + bb.w);
    }
}

// ============================================================
// Kernel B: persistent LSTM scan, ONE grid barrier per step.
// 128 blocks = 32 u-groups (16 units, all 4 gates) x 4 batch-groups (16 b).
//   smem: Wh_s [512 k][64 c] natural (128 KB) + h_s [512 u][32] dup (64 KB).
//   Intra-block 4-way k-split by warp pair; reduce in smem (reuses h_s).
//   h streamed via cp.async.cg in 4 chunks from duplicated mirror g_hTd.
// ============================================================
#define SMEM_SCAN ((512 * 64 + 512 * 32) * 4)   // 131072 + 65536 = 196608 B

__global__ void __launch_bounds__(256, 1) lstm_scan(const float* __restrict__ Wh)
{
    extern __shared__ float smem[];
    float* Wh_s = smem;                 // [512][64]
    float* h_s  = smem + 512 * 64;      // [512][32] duplicated (h,h); reused as red buffer

    int tid = threadIdx.x;
    int bid = blockIdx.x;
    int ug = bid >> 2, bg = bid & 3;
    int u0 = ug * 16, b0 = bg * 16;

    // stage Wh slice once: col c = g*16 + j  ->  global col g*512 + u0 + j
    #pragma unroll
    for (int i = 0; i < 128; i++) {
        int idx = tid + i * 256;              // 0..32767
        int k = idx >> 6, c = idx & 63;
        Wh_s[idx] = Wh[(size_t)k * G_ + (c >> 4) * 512 + u0 + (c & 15)];
    }

    // phase-1 coords: k-slice s (2 warps each), pos = 8 cx (8 cols) x 8 by (2 b)
    int s = tid >> 6;                    // 0..3
    int pos = tid & 63;
    int cx = pos & 7, by = pos >> 3;
    int cx8 = cx * 8, by4 = by * 4;
    // phase-2 coords: one cell; j contiguous for coalesced xg/g_hs access
    int jj = tid & 15;                   // unit-local 0..15
    int bcell = tid >> 4;                // batch-local 0..15
    int u_cell = u0 + jj;
    int b_cell = b0 + bcell;
    float creg = 0.0f;

    uint32_t hs_base = (uint32_t)__cvta_generic_to_shared(h_s);
    ull* redp = (ull*)h_s;               // reduce buffer overlays h_s (16 KB)
    const float* redf = (const float*)h_s;

    __syncthreads();                     // Wh_s ready

    for (int t = 0; t < T_; t++) {
        // prefetch xg for phase 2 (coalesced 64B runs over jj)
        float xgv[4];
        {
            size_t xoff = ((size_t)(b_cell * T_ + t)) * G_;
            #pragma unroll
            for (int g = 0; g < 4; g++)
                xgv[g] = g_xg[xoff + g * 512 + u_cell];
        }

        if (t > 0) {
            // issue all 4 h chunks (16 KB each), one commit group per chunk
            #pragma unroll
            for (int g = 0; g < 4; g++) {
                #pragma unroll
                for (int q = 0; q < 4; q++) {
                    int f = tid + q * 256;             // 0..1023 float4s in group
                    int u = g * 128 + (f >> 3);
                    int off = f & 7;
                    CP_ASYNC16(hs_base + (unsigned)(g * 1024 + f) * 16,
                               (const void*)&g_hTd[(size_t)u * 128 + bg * 32 + off * 4]);
                }
                CP_COMMIT();
            }
        } else {
            #pragma unroll
            for (int i = 0; i < 16; i++)
                *(float4*)&h_s[(tid + i * 256) * 4] = make_float4(0.f, 0.f, 0.f, 0.f);
        }

        ull acc2[8] = {};   // [colpair p][batch bb]: q = p*2 + bb

        #pragma unroll
        for (int ch = 0; ch < 4; ch++) {
            if (t > 0) {
                switch (ch) {            // wait until chunks 0..ch have landed
                    case 0: CP_WAIT(3); break;
                    case 1: CP_WAIT(2); break;
                    case 2: CP_WAIT(1); break;
                    default: CP_WAIT(0); break;
                }
            }
            __syncthreads();
            #pragma unroll 8
            for (int i = 0; i < 32; i++) {
                int k = (ch << 7) + (i << 2) + s;      // strided k-slice
                ulonglong2 wq0 = *(const ulonglong2*)&Wh_s[k * 64 + cx8];
                ulonglong2 wq1 = *(const ulonglong2*)&Wh_s[k * 64 + cx8 + 4];
                ulonglong2 hq  = *(const ulonglong2*)&h_s[k * 32 + by4];
                FMA2(acc2[0], hq.x, wq0.x, acc2[0]);
                FMA2(acc2[1], hq.y, wq0.x, acc2[1]);
                FMA2(acc2[2], hq.x, wq0.y, acc2[2]);
                FMA2(acc2[3], hq.y, wq0.y, acc2[3]);
                FMA2(acc2[4], hq.x, wq1.x, acc2[4]);
                FMA2(acc2[5], hq.y, wq1.x, acc2[5]);
                FMA2(acc2[6], hq.x, wq1.y, acc2[6]);
                FMA2(acc2[7], hq.y, wq1.y, acc2[7]);
            }
        }

        // intra-block k-reduce via smem (overlays h_s; all h reads done)
        __syncthreads();
        #pragma unroll
        for (int q = 0; q < 8; q++)
            redp[(pos * 4 + s) * 8 + q] = acc2[q];
        __syncthreads();

        // phase 2: one cell per thread (block-local!)
        {
            float sum[4];
            #pragma unroll
            for (int g = 0; g < 4; g++) {
                int c = g * 16 + jj;
                int cx2 = c >> 3, c8v = c & 7;
                int p = c8v >> 1, elem = c8v & 1;
                int pos2 = (bcell >> 1) * 8 + cx2;
                int bb = bcell & 1;
                int base = ((pos2 * 4) * 8 + (p * 2 + bb)) * 2 + elem;
                float v = redf[base] + redf[base + 16] + redf[base + 32] + redf[base + 48];
                sum[g] = v + xgv[g];
            }
            float ig = 1.0f / (1.0f + expf(-sum[0]));
            float jg = tanhf(sum[1]);
            float fg = 1.0f / (1.0f + expf(-(sum[2] + 1.0f)));  // forget_bias = 1
            float og = 1.0f / (1.0f + expf(-sum[3]));
            creg = fg * creg + ig * jg;
            float h = og * tanhf(creg);
            *(float2*)&g_hTd[(size_t)u_cell * 128 + b_cell * 2] = make_float2(h, h);
            g_hs[((size_t)(b_cell * T_ + t)) * H_ + u_cell] = h;
        }
        grid_barrier(NBLK);
    }
}

// ============================================================
// Kernel C: logits = sigmoid(hs@Wd + bd); per-block partial MSE (f32x2 packed)
// ============================================================
__global__ void __launch_bounds__(256) out_loss(
    const float* __restrict__ Wd, const float* __restrict__ bd,
    const float* __restrict__ Y)
{
    __shared__ float h_s[512 * 20];
    __shared__ float red[8];
    int tid = threadIdx.x;
    int row0 = blockIdx.x * 16;

    #pragma unroll
    for (int i = 0; i < 32; i++) {
        int idx = tid + i * 256;
        int r = idx >> 9, k = idx & 511;
        h_s[k * 20 + r] = g_hs[(size_t)(row0 + r) * H_ + k];
    }
    __syncthreads();

    int cc = tid & 127;
    int rh = tid >> 7;
    ull acc2[4] = {};
    #pragma unroll 4
    for (int k = 0; k < 512; k++) {
        float w = Wd[(size_t)k * N_ + cc];
        ull wd; PACK2(wd, w, w);
        ulonglong2 ha = *(const ulonglong2*)&h_s[k * 20 + rh * 8];
        ulonglong2 hb = *(const ulonglong2*)&h_s[k * 20 + rh * 8 + 4];
        FMA2(acc2[0], ha.x, wd, acc2[0]);
        FMA2(acc2[1], ha.y, wd, acc2[1]);
        FMA2(acc2[2], hb.x, wd, acc2[2]);
        FMA2(acc2[3], hb.y, wd, acc2[3]);
    }
    float accv[8];
    #pragma unroll
    for (int p = 0; p < 4; p++) UNPACK2(accv[2 * p], accv[2 * p + 1], acc2[p]);

    float bdc = bd[cc];
    float lsum = 0.0f;
    #pragma unroll
    for (int i = 0; i < 8; i++) {
        int row = row0 + rh * 8 + i;
        float logit = 1.0f / (1.0f + expf(-(accv[i] + bdc)));
        float d = Y[(size_t)row * N_ + cc] - logit;
        lsum += d * d;
    }
    #pragma unroll
    for (int o = 16; o; o >>= 1) lsum += __shfl_xor_sync(0xFFFFFFFFu, lsum, o);
    if ((tid & 31) == 0) red[tid >> 5] = lsum;
    __syncthreads();
    if (tid == 0) {
        float ssum = 0.0f;
        #pragma unroll
        for (int i = 0; i < 8; i++) ssum += red[i];
        g_lpart[blockIdx.x] = ssum;
    }
}

// ============================================================
// Kernel D: final deterministic reduction -> loss scalar
// ============================================================
__global__ void finalize(float* __restrict__ out)
{
    __shared__ float red[8];
    int tid = threadIdx.x;
    float sv = 0.0f;
    for (int i = tid; i < 2048; i += 256) sv += g_lpart[i];
    #pragma unroll
    for (int o = 16; o; o >>= 1) sv += __shfl_xor_sync(0xFFFFFFFFu, sv, o);
    if ((tid & 31) == 0) red[tid >> 5] = sv;
    __syncthreads();
    if (tid == 0) {
        float tt = 0.0f;
        #pragma unroll
        for (int i = 0; i < 8; i++) tt += red[i];
        out[0] = tt * (100.0f / ((float)B_ * (float)T_ * (float)N_));
    }
}

// ============================================================
extern "C" void kernel_launch(void* const* d_in, const int* in_sizes, int n_in,
                              void* d_out, int out_size)
{
    const float* X  = (const float*)d_in[0];
    const float* Y  = (const float*)d_in[1];
    const float* Wx = (const float*)d_in[2];
    const float* Wh = (const float*)d_in[3];
    const float* b  = (const float*)d_in[4];
    const float* Wd = (const float*)d_in[5];
    const float* bd = (const float*)d_in[6];
    (void)in_sizes; (void)n_in; (void)out_size;

    cudaFuncSetAttribute(lstm_scan, cudaFuncAttributeMaxDynamicSharedMemorySize, SMEM_SCAN);

    dim3 gA(G_ / 64, BT_ / 64);                 // 32 x 512
    xg_gemm<<<gA, 256>>>(X, Wx, b);
    lstm_scan<<<NBLK, 256, SMEM_SCAN>>>(Wh);
    out_loss<<<BT_ / 16, 256>>>(Wd, bd, Y);     // 2048 blocks
    finalize<<<1, 256>>>((float*)d_out);
}

// round 6
// speedup vs baseline: 1.4934x; 1.2617x over previous
#include <cuda_runtime.h>
#include <cstdint>
#include <math.h>

#define B_  64
#define T_  512
#define N_  128
#define H_  512
#define G_  2048              // 4*H
#define BT_ (B_ * T_)         // 32768
#define NBLK 128              // persistent scan blocks (1/SM, all co-resident)

typedef unsigned long long ull;

// packed f32x2 helpers
#define FMA2(d, a, b, c) asm("fma.rn.f32x2 %0, %1, %2, %3;" : "=l"(d) : "l"(a), "l"(b), "l"(c))
#define PACK2(d, lo, hi) asm("mov.b64 %0, {%1, %2};" : "=l"(d) : "f"(lo), "f"(hi))
#define UNPACK2(lo, hi, v) asm("mov.b64 {%0, %1}, %2;" : "=f"(lo), "=f"(hi) : "l"(v))

// cp.async helpers (.cg = L1-bypass, L2-direct: cross-SM coherent)
#define CP_ASYNC16(dst_smem_u32, src_gmem_ptr) \
    asm volatile("cp.async.cg.shared.global [%0], [%1], 16;" :: "r"(dst_smem_u32), "l"(src_gmem_ptr) : "memory")
#define CP_COMMIT() asm volatile("cp.async.commit_group;" ::: "memory")
#define CP_WAIT(n)  asm volatile("cp.async.wait_group %0;" :: "n"(n) : "memory")

// -------- device scratch (allocation-free rule: __device__ globals) --------
__device__ float g_xg[(size_t)BT_ * G_];     // 268 MB: X@Wx + b, [bt][4H]
__device__ float g_hs[(size_t)BT_ * H_];     // 67 MB: h history [b][t][H] (for out_loss)
__device__ float g_hTd[2][H_ * 2 * B_];      // 2x256 KB: h double-buffered, dup [u][(h,h) x 64]
__device__ float g_lpart[2048];              // per-block loss partials
__device__ volatile int g_flags[128];        // [bg*32 + ug] = steps completed (reset by xg_gemm)

// ============================================================
// Kernel A: xg = X @ Wx + b   (M=32768, K=128, N=2048), f32x2 packed
// Also resets the scan sync flags (stream-ordered before lstm_scan).
// ============================================================
__global__ void __launch_bounds__(256) xg_gemm(
    const float* __restrict__ X, const float* __restrict__ Wx,
    const float* __restrict__ bias)
{
    __shared__ float Xst[64 * 68];    // [k][row], transposed X tile
    __shared__ float Wsd[64 * 128];   // [k][col-dup]: (w0,w0,w1,w1,...)
    int tid = threadIdx.x;
    if (blockIdx.x == 0 && blockIdx.y == 0 && tid < 128) g_flags[tid] = 0;

    int m0 = blockIdx.y * 64;
    int n0 = blockIdx.x * 64;
    int cx = tid & 15, ry = tid >> 4;
    int c8 = cx * 8;

    ull acc[2][4] = {};

    for (int kc = 0; kc < 128; kc += 64) {
        __syncthreads();
        #pragma unroll
        for (int i = 0; i < 16; i++) {
            int idx = tid + i * 256;
            int k = idx & 63, r = idx >> 6;
            Xst[k * 68 + r] = X[(size_t)(m0 + r) * 128 + kc + k];
        }
        #pragma unroll
        for (int i = 0; i < 32; i++) {
            int idx = tid + i * 256;
            int k = idx >> 7, rem = idx & 127;
            Wsd[k * 128 + rem] = Wx[(size_t)(kc + k) * G_ + n0 + (rem >> 1)];
        }
        __syncthreads();
        #pragma unroll 8
        for (int k = 0; k < 64; k++) {
            ulonglong2 hq  = *(const ulonglong2*)&Xst[k * 68 + ry * 4];
            ulonglong2 wq0 = *(const ulonglong2*)&Wsd[k * 128 + c8];
            ulonglong2 wq1 = *(const ulonglong2*)&Wsd[k * 128 + c8 + 4];
            FMA2(acc[0][0], hq.x, wq0.x, acc[0][0]);
            FMA2(acc[0][1], hq.x, wq0.y, acc[0][1]);
            FMA2(acc[0][2], hq.x, wq1.x, acc[0][2]);
            FMA2(acc[0][3], hq.x, wq1.y, acc[0][3]);
            FMA2(acc[1][0], hq.y, wq0.x, acc[1][0]);
            FMA2(acc[1][1], hq.y, wq0.y, acc[1][1]);
            FMA2(acc[1][2], hq.y, wq1.x, acc[1][2]);
            FMA2(acc[1][3], hq.y, wq1.y, acc[1][3]);
        }
    }
    float4 bb = *(const float4*)&bias[n0 + cx * 4];
    #pragma unroll
    for (int j = 0; j < 2; j++) {
        float lo[4], hi[4];
        #pragma unroll
        for (int cp = 0; cp < 4; cp++) UNPACK2(lo[cp], hi[cp], acc[j][cp]);
        int row0 = m0 + ry * 4 + j * 2;
        *(float4*)&g_xg[(size_t)row0 * G_ + n0 + cx * 4] =
            make_float4(lo[0] + bb.x, lo[1] + bb.y, lo[2] + bb.z, lo[3] + bb.w);
        *(float4*)&g_xg[(size_t)(row0 + 1) * G_ + n0 + cx * 4] =
            make_float4(hi[0] + bb.x, hi[1] + bb.y, hi[2] + bb.z, hi[3] + bb.w);
    }
}

// ============================================================
// Kernel B: persistent LSTM scan, decentralized per-bg-group sync.
// 128 blocks = 32 u-groups (16 units, all 4 gates) x 4 batch-groups (16 b).
//   smem: Wh_s [512 k][64 c] natural (128 KB) + h_s [512 u][32] dup (64 KB).
//   Conflict-free weight LDS: thread cx reads 2 contiguous 16B chunks.
//   Sync: producer flags per (bg, ug); consumer waits only on its bg's 32.
//   h double-buffered in g_hTd; streamed via cp.async.cg in 4 chunks.
// ============================================================
#define SMEM_SCAN ((512 * 64 + 512 * 32) * 4)   // 131072 + 65536 = 196608 B

__global__ void __launch_bounds__(256, 1) lstm_scan(const float* __restrict__ Wh)
{
    extern __shared__ float smem[];
    float* Wh_s = smem;                 // [512][64]
    float* h_s  = smem + 512 * 64;      // [512][32] dup (h,h); reused as red buffer

    int tid = threadIdx.x;
    int bid = blockIdx.x;
    int ug = bid >> 2, bg = bid & 3;
    int u0 = ug * 16, b0 = bg * 16;

    // stage Wh slice once: col c = g*16 + j  ->  global col g*512 + u0 + j
    #pragma unroll
    for (int i = 0; i < 128; i++) {
        int idx = tid + i * 256;              // 0..32767
        int k = idx >> 6, c = idx & 63;
        Wh_s[idx] = Wh[(size_t)k * G_ + (c >> 4) * 512 + u0 + (c & 15)];
    }

    // phase-1 coords: k-slice s (2 warps each), pos = cx (0..7) x by (0..7)
    int s = tid >> 6;                    // 0..3
    int pos = tid & 63;
    int cx = pos & 7, by = pos >> 3;
    int cx4 = cx * 4, by4 = by * 4;
    // phase-2 coords: one cell
    int jj = tid & 15;                   // unit-local 0..15
    int bcell = tid >> 4;                // batch-local 0..15
    int u_cell = u0 + jj;
    int b_cell = b0 + bcell;
    float creg = 0.0f;

    uint32_t hs_base = (uint32_t)__cvta_generic_to_shared(h_s);
    ull* redp = (ull*)h_s;               // reduce buffer overlays h_s (16 KB)
    const float* redf = (const float*)h_s;

    __syncthreads();                     // Wh_s ready

    for (int t = 0; t < T_; t++) {
        // prefetch xg for phase 2 (independent of sync)
        float xgv[4];
        {
            size_t xoff = ((size_t)(b_cell * T_ + t)) * G_;
            #pragma unroll
            for (int g = 0; g < 4; g++)
                xgv[g] = g_xg[xoff + g * 512 + u_cell];
        }

        if (t > 0) {
            // wait for all 32 producers of this bg group to finish step t-1
            if (tid < 32) {
                while (g_flags[bg * 32 + tid] < t) { }
                __threadfence();
            }
            __syncthreads();
            const float* src = g_hTd[t & 1];
            // issue all 4 h chunks (16 KB each), one commit group per chunk
            #pragma unroll
            for (int g = 0; g < 4; g++) {
                #pragma unroll
                for (int q = 0; q < 4; q++) {
                    int f = tid + q * 256;             // 0..1023 float4s in group
                    int u = g * 128 + (f >> 3);
                    int off = f & 7;
                    CP_ASYNC16(hs_base + (unsigned)(g * 1024 + f) * 16,
                               (const void*)&src[(size_t)u * 128 + bg * 32 + off * 4]);
                }
                CP_COMMIT();
            }
        } else {
            #pragma unroll
            for (int i = 0; i < 16; i++)
                *(float4*)&h_s[(tid + i * 256) * 4] = make_float4(0.f, 0.f, 0.f, 0.f);
        }

        ull acc2[8] = {};   // slot = psIdx*2 + bl; pairs {2cx,2cx+1,16+2cx,17+2cx}

        #pragma unroll
        for (int ch = 0; ch < 4; ch++) {
            if (t > 0) {
                switch (ch) {            // wait until chunks 0..ch have landed
                    case 0: CP_WAIT(3); break;
                    case 1: CP_WAIT(2); break;
                    case 2: CP_WAIT(1); break;
                    default: CP_WAIT(0); break;
                }
            }
            __syncthreads();
            #pragma unroll 8
            for (int i = 0; i < 32; i++) {
                int k = (ch << 7) + (i << 2) + s;      // strided k-slice
                // conflict-free: 8 threads x 16B contiguous per load
                ulonglong2 wq0 = *(const ulonglong2*)&Wh_s[k * 64 + cx4];        // pairs 2cx,2cx+1
                ulonglong2 wq1 = *(const ulonglong2*)&Wh_s[k * 64 + 32 + cx4];   // pairs 16+2cx,17+2cx
                ulonglong2 hq  = *(const ulonglong2*)&h_s[k * 32 + by4];         // b=2by, 2by+1 (dup)
                FMA2(acc2[0], hq.x, wq0.x, acc2[0]);
                FMA2(acc2[1], hq.y, wq0.x, acc2[1]);
                FMA2(acc2[2], hq.x, wq0.y, acc2[2]);
                FMA2(acc2[3], hq.y, wq0.y, acc2[3]);
                FMA2(acc2[4], hq.x, wq1.x, acc2[4]);
                FMA2(acc2[5], hq.y, wq1.x, acc2[5]);
                FMA2(acc2[6], hq.x, wq1.y, acc2[6]);
                FMA2(acc2[7], hq.y, wq1.y, acc2[7]);
            }
        }

        // intra-block k-reduce via smem (overlays h_s; all h reads done)
        __syncthreads();
        #pragma unroll
        for (int q = 0; q < 8; q++)
            redp[(pos * 4 + s) * 8 + q] = acc2[q];
        __syncthreads();

        // phase 2: one cell per thread (block-local)
        {
            float sum[4];
            #pragma unroll
            for (int g = 0; g < 4; g++) {
                int c = g * 16 + jj;          // local col
                int q_c = c >> 1, elem = c & 1;
                int cxm, psIdx;
                if (q_c < 16) { cxm = q_c >> 1; psIdx = q_c & 1; }
                else          { cxm = (q_c - 16) >> 1; psIdx = 2 + (q_c & 1); }
                int bym = bcell >> 1, bl = bcell & 1;
                int posm = bym * 8 + cxm;
                int base = ((posm * 4) * 8 + (psIdx * 2 + bl)) * 2 + elem;
                float v = redf[base] + redf[base + 16] + redf[base + 32] + redf[base + 48];
                sum[g] = v + xgv[g];
            }
            float ig = 1.0f / (1.0f + expf(-sum[0]));
            float jg = tanhf(sum[1]);
            float fg = 1.0f / (1.0f + expf(-(sum[2] + 1.0f)));  // forget_bias = 1
            float og = 1.0f / (1.0f + expf(-sum[3]));
            creg = fg * creg + ig * jg;
            float h = og * tanhf(creg);
            *(float2*)&g_hTd[(t + 1) & 1][(size_t)u_cell * 128 + b_cell * 2] = make_float2(h, h);
            g_hs[((size_t)(b_cell * T_ + t)) * H_ + u_cell] = h;
        }
        __syncthreads();                          // all h writes + redf reads done
        if (tid == 0) {
            __threadfence();                      // release h writes to L2/GPU scope
            g_flags[bg * 32 + ug] = t + 1;
        }
    }
}

// ============================================================
// Kernel C: logits = sigmoid(hs@Wd + bd); per-block partial MSE (f32x2 packed)
// ============================================================
__global__ void __launch_bounds__(256) out_loss(
    const float* __restrict__ Wd, const float* __restrict__ bd,
    const float* __restrict__ Y)
{
    __shared__ float h_s[512 * 20];
    __shared__ float red[8];
    int tid = threadIdx.x;
    int row0 = blockIdx.x * 16;

    #pragma unroll
    for (int i = 0; i < 32; i++) {
        int idx = tid + i * 256;
        int r = idx >> 9, k = idx & 511;
        h_s[k * 20 + r] = g_hs[(size_t)(row0 + r) * H_ + k];
    }
    __syncthreads();

    int cc = tid & 127;
    int rh = tid >> 7;
    ull acc2[4] = {};
    #pragma unroll 4
    for (int k = 0; k < 512; k++) {
        float w = Wd[(size_t)k * N_ + cc];
        ull wd; PACK2(wd, w, w);
        ulonglong2 ha = *(const ulonglong2*)&h_s[k * 20 + rh * 8];
        ulonglong2 hb = *(const ulonglong2*)&h_s[k * 20 + rh * 8 + 4];
        FMA2(acc2[0], ha.x, wd, acc2[0]);
        FMA2(acc2[1], ha.y, wd, acc2[1]);
        FMA2(acc2[2], hb.x, wd, acc2[2]);
        FMA2(acc2[3], hb.y, wd, acc2[3]);
    }
    float accv[8];
    #pragma unroll
    for (int p = 0; p < 4; p++) UNPACK2(accv[2 * p], accv[2 * p + 1], acc2[p]);

    float bdc = bd[cc];
    float lsum = 0.0f;
    #pragma unroll
    for (int i = 0; i < 8; i++) {
        int row = row0 + rh * 8 + i;
        float logit = 1.0f / (1.0f + expf(-(accv[i] + bdc)));
        float d = Y[(size_t)row * N_ + cc] - logit;
        lsum += d * d;
    }
    #pragma unroll
    for (int o = 16; o; o >>= 1) lsum += __shfl_xor_sync(0xFFFFFFFFu, lsum, o);
    if ((tid & 31) == 0) red[tid >> 5] = lsum;
    __syncthreads();
    if (tid == 0) {
        float ssum = 0.0f;
        #pragma unroll
        for (int i = 0; i < 8; i++) ssum += red[i];
        g_lpart[blockIdx.x] = ssum;
    }
}

// ============================================================
// Kernel D: final deterministic reduction -> loss scalar
// ============================================================
__global__ void finalize(float* __restrict__ out)
{
    __shared__ float red[8];
    int tid = threadIdx.x;
    float sv = 0.0f;
    for (int i = tid; i < 2048; i += 256) sv += g_lpart[i];
    #pragma unroll
    for (int o = 16; o; o >>= 1) sv += __shfl_xor_sync(0xFFFFFFFFu, sv, o);
    if ((tid & 31) == 0) red[tid >> 5] = sv;
    __syncthreads();
    if (tid == 0) {
        float tt = 0.0f;
        #pragma unroll
        for (int i = 0; i < 8; i++) tt += red[i];
        out[0] = tt * (100.0f / ((float)B_ * (float)T_ * (float)N_));
    }
}

// ============================================================
extern "C" void kernel_launch(void* const* d_in, const int* in_sizes, int n_in,
                              void* d_out, int out_size)
{
    const float* X  = (const float*)d_in[0];
    const float* Y  = (const float*)d_in[1];
    const float* Wx = (const float*)d_in[2];
    const float* Wh = (const float*)d_in[3];
    const float* b  = (const float*)d_in[4];
    const float* Wd = (const float*)d_in[5];
    const float* bd = (const float*)d_in[6];
    (void)in_sizes; (void)n_in; (void)out_size;

    cudaFuncSetAttribute(lstm_scan, cudaFuncAttributeMaxDynamicSharedMemorySize, SMEM_SCAN);

    dim3 gA(G_ / 64, BT_ / 64);                 // 32 x 512
    xg_gemm<<<gA, 256>>>(X, Wx, b);             // also resets g_flags
    lstm_scan<<<NBLK, 256, SMEM_SCAN>>>(Wh);
    out_loss<<<BT_ / 16, 256>>>(Wd, bd, Y);     // 2048 blocks
    finalize<<<1, 256>>>((float*)d_out);
}

// round 7
// speedup vs baseline: 1.9700x; 1.3192x over previous
#include <cuda_runtime.h>
#include <cstdint>
#include <math.h>

#define B_  64
#define T_  512
#define N_  128
#define H_  512
#define G_  2048              // 4*H
#define BT_ (B_ * T_)         // 32768
#define NBLK 128

typedef unsigned long long ull;

#define FMA2(d, a, b, c) asm("fma.rn.f32x2 %0, %1, %2, %3;" : "=l"(d) : "l"(a), "l"(b), "l"(c))
#define ADD2(d, a, b)    asm("add.rn.f32x2 %0, %1, %2;" : "=l"(d) : "l"(a), "l"(b))
#define PACK2(d, lo, hi) asm("mov.b64 %0, {%1, %2};" : "=l"(d) : "f"(lo), "f"(hi))
#define UNPACK2(lo, hi, v) asm("mov.b64 {%0, %1}, %2;" : "=f"(lo), "=f"(hi) : "l"(v))

#define CP_ASYNC16(dst_smem_u32, src_gmem_ptr) \
    asm volatile("cp.async.cg.shared.global [%0], [%1], 16;" :: "r"(dst_smem_u32), "l"(src_gmem_ptr) : "memory")
#define CP_COMMIT() asm volatile("cp.async.commit_group;" ::: "memory")
#define CP_WAIT(n)  asm volatile("cp.async.wait_group %0;" :: "n"(n) : "memory")

// -------- device scratch --------
__device__ float g_xg[(size_t)BT_ * G_];     // X@Wx + b, [bt][4H]
__device__ float g_hs[(size_t)BT_ * H_];     // h history [b][t][H]
__device__ float g_hT[2][H_ * B_];           // h double-buffered, [u][b] (non-dup)
__device__ float g_lpart[2048];
__device__ volatile int g_flags[128];        // [bg*32 + ug] (reset by xg_gemm)

// ============================================================
// Kernel A: xg = X @ Wx + b  (unchanged from R6; also resets flags)
// ============================================================
__global__ void __launch_bounds__(256) xg_gemm(
    const float* __restrict__ X, const float* __restrict__ Wx,
    const float* __restrict__ bias)
{
    __shared__ float Xst[64 * 68];
    __shared__ float Wsd[64 * 128];
    int tid = threadIdx.x;
    if (blockIdx.x == 0 && blockIdx.y == 0 && tid < 128) g_flags[tid] = 0;

    int m0 = blockIdx.y * 64;
    int n0 = blockIdx.x * 64;
    int cx = tid & 15, ry = tid >> 4;
    int c8 = cx * 8;

    ull acc[2][4] = {};
    for (int kc = 0; kc < 128; kc += 64) {
        __syncthreads();
        #pragma unroll
        for (int i = 0; i < 16; i++) {
            int idx = tid + i * 256;
            int k = idx & 63, r = idx >> 6;
            Xst[k * 68 + r] = X[(size_t)(m0 + r) * 128 + kc + k];
        }
        #pragma unroll
        for (int i = 0; i < 32; i++) {
            int idx = tid + i * 256;
            int k = idx >> 7, rem = idx & 127;
            Wsd[k * 128 + rem] = Wx[(size_t)(kc + k) * G_ + n0 + (rem >> 1)];
        }
        __syncthreads();
        #pragma unroll 8
        for (int k = 0; k < 64; k++) {
            ulonglong2 hq  = *(const ulonglong2*)&Xst[k * 68 + ry * 4];
            ulonglong2 wq0 = *(const ulonglong2*)&Wsd[k * 128 + c8];
            ulonglong2 wq1 = *(const ulonglong2*)&Wsd[k * 128 + c8 + 4];
            FMA2(acc[0][0], hq.x, wq0.x, acc[0][0]);
            FMA2(acc[0][1], hq.x, wq0.y, acc[0][1]);
            FMA2(acc[0][2], hq.x, wq1.x, acc[0][2]);
            FMA2(acc[0][3], hq.x, wq1.y, acc[0][3]);
            FMA2(acc[1][0], hq.y, wq0.x, acc[1][0]);
            FMA2(acc[1][1], hq.y, wq0.y, acc[1][1]);
            FMA2(acc[1][2], hq.y, wq1.x, acc[1][2]);
            FMA2(acc[1][3], hq.y, wq1.y, acc[1][3]);
        }
    }
    float4 bb = *(const float4*)&bias[n0 + cx * 4];
    #pragma unroll
    for (int j = 0; j < 2; j++) {
        float lo[4], hi[4];
        #pragma unroll
        for (int cp = 0; cp < 4; cp++) UNPACK2(lo[cp], hi[cp], acc[j][cp]);
        int row0 = m0 + ry * 4 + j * 2;
        *(float4*)&g_xg[(size_t)row0 * G_ + n0 + cx * 4] =
            make_float4(lo[0] + bb.x, lo[1] + bb.y, lo[2] + bb.z, lo[3] + bb.w);
        *(float4*)&g_xg[(size_t)(row0 + 1) * G_ + n0 + cx * 4] =
            make_float4(hi[0] + bb.x, hi[1] + bb.y, hi[2] + bb.z, hi[3] + bb.w);
    }
}

// ============================================================
// Kernel B: persistent LSTM scan, 8x8 register tiles, 1.0 MAC/byte.
// Block (ug, bg): 64 cols (4 gates x 16 units) x 16 batches, K=512.
// Thread (cg:8, bh:2, kq:16): 8 cols x 8 batches x 32 ks.
//   smem: Wh_s [512][64] 16B-chunk XOR-swizzled (128 KB)
//         scr 64KB: h_s [512][16] swizzled (32KB) / reduce buffer (64KB)
//         gsum [16][64] + hstage [16][16]
// ============================================================
#define SMEM_SCAN ((32768 + 16384 + 1024 + 256) * 4)   // 201728 B

__global__ void __launch_bounds__(256, 1) lstm_scan(const float* __restrict__ Wh)
{
    extern __shared__ float smem[];
    float* Wh_s   = smem;                 // [512][64] swizzled
    float* scr    = smem + 32768;         // h_s / redU
    float* gsum   = smem + 32768 + 16384; // [16 b][64 c]
    float* hstage = gsum + 1024;          // [16 u][16 b]

    int tid = threadIdx.x;
    int bid = blockIdx.x;
    int ug = bid >> 2, bg = bid & 3;
    int u0 = ug * 16;

    // stage Wh once, 16B-chunk swizzle: row k, logical chunk s -> phys s^(k&7)
    for (int i = 0; i < 128; i++) {
        int idx = tid + i * 256;              // 0..32767
        int k = idx >> 6, c = idx & 63;
        int s = c >> 2, j = c & 3;
        Wh_s[k * 64 + ((s ^ (k & 7)) << 2) + j] =
            Wh[(size_t)k * G_ + (c >> 4) * 512 + u0 + (c & 15)];
    }

    int cg = tid >> 5, bh = (tid >> 4) & 1, kq = tid & 15;
    int u_l = tid & 15, b_l = tid >> 4;       // phase-2 cell
    int u_cell = u0 + u_l, b_cell = bg * 16 + b_l;
    int c2r = tid & 31, bp = tid >> 5;        // sum-step coords
    float creg = 0.0f;

    uint32_t scr_base = (uint32_t)__cvta_generic_to_shared(scr);
    ull* redU = (ull*)scr;

    __syncthreads();

    for (int t = 0; t < T_; t++) {
        // prefetch xg (hides DRAM latency behind the flag wait)
        float xgv[4];
        {
            size_t xoff = ((size_t)(b_cell * T_ + t)) * G_;
            #pragma unroll
            for (int g = 0; g < 4; g++)
                xgv[g] = g_xg[xoff + g * 512 + u_cell];
        }

        if (t > 0) {
            if (tid < 32) {
                while (g_flags[bg * 32 + tid] < t) { __nanosleep(32); }
                __threadfence();
            }
            __syncthreads();
            const float* src = g_hT[t & 1];
            // 4 chunks of 8KB (u-range 128 each); swizzled dst
            #pragma unroll
            for (int ch = 0; ch < 4; ch++) {
                #pragma unroll
                for (int q2 = 0; q2 < 2; q2++) {
                    int f = ch * 512 + tid + q2 * 256;   // float4 id 0..2047
                    int u = f >> 2, q = f & 3;
                    int qp = q ^ ((u >> 1) & 3);
                    CP_ASYNC16(scr_base + (unsigned)(u * 64 + qp * 16),
                               (const void*)&src[(size_t)u * 64 + bg * 16 + q * 4]);
                }
                CP_COMMIT();
            }
        } else {
            #pragma unroll
            for (int i = 0; i < 8; i++)
                *(float4*)&scr[(tid + i * 256) * 4] = make_float4(0.f, 0.f, 0.f, 0.f);
        }

        ull acc[4][8] = {};   // [colpair cp][batch b]

        #pragma unroll
        for (int ch = 0; ch < 4; ch++) {
            if (t > 0) {
                switch (ch) {
                    case 0: CP_WAIT(3); break;
                    case 1: CP_WAIT(2); break;
                    case 2: CP_WAIT(1); break;
                    default: CP_WAIT(0); break;
                }
            }
            __syncthreads();
            #pragma unroll
            for (int ii = 0; ii < 8; ii++) {
                int k = (ch * 8 + ii) * 16 + kq;
                float4 w0 = *(const float4*)&Wh_s[k * 64 + (((cg * 2 + 0) ^ (k & 7)) << 2)];
                float4 w1 = *(const float4*)&Wh_s[k * 64 + (((cg * 2 + 1) ^ (k & 7)) << 2)];
                float4 h0 = *(const float4*)&scr[k * 16 + (((bh * 2 + 0) ^ ((k >> 1) & 3)) << 2)];
                float4 h1 = *(const float4*)&scr[k * 16 + (((bh * 2 + 1) ^ ((k >> 1) & 3)) << 2)];
                ull wp[4];
                PACK2(wp[0], w0.x, w0.y); PACK2(wp[1], w0.z, w0.w);
                PACK2(wp[2], w1.x, w1.y); PACK2(wp[3], w1.z, w1.w);
                ull hd;
                PACK2(hd, h0.x, h0.x);
                FMA2(acc[0][0], wp[0], hd, acc[0][0]); FMA2(acc[1][0], wp[1], hd, acc[1][0]);
                FMA2(acc[2][0], wp[2], hd, acc[2][0]); FMA2(acc[3][0], wp[3], hd, acc[3][0]);
                PACK2(hd, h0.y, h0.y);
                FMA2(acc[0][1], wp[0], hd, acc[0][1]); FMA2(acc[1][1], wp[1], hd, acc[1][1]);
                FMA2(acc[2][1], wp[2], hd, acc[2][1]); FMA2(acc[3][1], wp[3], hd, acc[3][1]);
                PACK2(hd, h0.z, h0.z);
                FMA2(acc[0][2], wp[0], hd, acc[0][2]); FMA2(acc[1][2], wp[1], hd, acc[1][2]);
                FMA2(acc[2][2], wp[2], hd, acc[2][2]); FMA2(acc[3][2], wp[3], hd, acc[3][2]);
                PACK2(hd, h0.w, h0.w);
                FMA2(acc[0][3], wp[0], hd, acc[0][3]); FMA2(acc[1][3], wp[1], hd, acc[1][3]);
                FMA2(acc[2][3], wp[2], hd, acc[2][3]); FMA2(acc[3][3], wp[3], hd, acc[3][3]);
                PACK2(hd, h1.x, h1.x);
                FMA2(acc[0][4], wp[0], hd, acc[0][4]); FMA2(acc[1][4], wp[1], hd, acc[1][4]);
                FMA2(acc[2][4], wp[2], hd, acc[2][4]); FMA2(acc[3][4], wp[3], hd, acc[3][4]);
                PACK2(hd, h1.y, h1.y);
                FMA2(acc[0][5], wp[0], hd, acc[0][5]); FMA2(acc[1][5], wp[1], hd, acc[1][5]);
                FMA2(acc[2][5], wp[2], hd, acc[2][5]); FMA2(acc[3][5], wp[3], hd, acc[3][5]);
                PACK2(hd, h1.z, h1.z);
                FMA2(acc[0][6], wp[0], hd, acc[0][6]); FMA2(acc[1][6], wp[1], hd, acc[1][6]);
                FMA2(acc[2][6], wp[2], hd, acc[2][6]); FMA2(acc[3][6], wp[3], hd, acc[3][6]);
                PACK2(hd, h1.w, h1.w);
                FMA2(acc[0][7], wp[0], hd, acc[0][7]); FMA2(acc[1][7], wp[1], hd, acc[1][7]);
                FMA2(acc[2][7], wp[2], hd, acc[2][7]); FMA2(acc[3][7], wp[3], hd, acc[3][7]);
            }
        }

        // ---- 16-way k-reduce through swizzled smem buffer ----
        __syncthreads();          // all h_s reads done; scr becomes redU
        #pragma unroll
        for (int cp = 0; cp < 4; cp++) {
            int c2w = cg * 4 + cp;
            #pragma unroll
            for (int b = 0; b < 8; b++) {
                int L = ((c2w * 16) + (bh * 8 + b)) * 16 + kq;  // ull index
                int I = (L >> 1) ^ (c2w & 7);                   // swizzled 16B block
                redU[(I << 1) | (L & 1)] = acc[cp][b];
            }
        }
        __syncthreads();

        // sum step: thread (c2r 0..31, bp 0..7) -> cols (2c2r, 2c2r+1), batches (2bp, 2bp+1)
        #pragma unroll
        for (int j = 0; j < 2; j++) {
            int bJ = bp * 2 + j;
            int Ibase = (c2r * 16 + bJ) * 8;
            ull a0 = 0ull, a1 = 0ull;
            #pragma unroll
            for (int m = 0; m < 8; m += 2) {
                int Ip0 = (Ibase + m) ^ (c2r & 7);
                int Ip1 = (Ibase + m + 1) ^ (c2r & 7);
                ulonglong2 v0 = *(const ulonglong2*)&redU[Ip0 << 1];
                ulonglong2 v1 = *(const ulonglong2*)&redU[Ip1 << 1];
                ADD2(a0, a0, v0.x); ADD2(a0, a0, v0.y);
                ADD2(a1, a1, v1.x); ADD2(a1, a1, v1.y);
            }
            ADD2(a0, a0, a1);
            float s0, s1; UNPACK2(s0, s1, a0);
            *(float2*)&gsum[bJ * 64 + c2r * 2] = make_float2(s0, s1);
        }
        __syncthreads();

        // phase 2: one cell per thread
        {
            float s0 = gsum[b_l * 64 + 0 * 16 + u_l] + xgv[0];   // i
            float s1 = gsum[b_l * 64 + 1 * 16 + u_l] + xgv[1];   // j
            float s2 = gsum[b_l * 64 + 2 * 16 + u_l] + xgv[2];   // f
            float s3 = gsum[b_l * 64 + 3 * 16 + u_l] + xgv[3];   // o
            float ig = 1.0f / (1.0f + expf(-s0));
            float jg = tanhf(s1);
            float fg = 1.0f / (1.0f + expf(-(s2 + 1.0f)));       // forget_bias = 1
            float og = 1.0f / (1.0f + expf(-s3));
            creg = fg * creg + ig * jg;
            float h = og * tanhf(creg);
            hstage[u_l * 16 + b_l] = h;
            g_hs[((size_t)(b_cell * T_ + t)) * H_ + u_cell] = h;
        }
        __syncthreads();
        if (tid < 64) {        // coalesced h mirror write
            int u = tid >> 2, q = tid & 3;
            *(float4*)&g_hT[(t + 1) & 1][(size_t)(u0 + u) * 64 + bg * 16 + q * 4] =
                *(const float4*)&hstage[u * 16 + q * 4];
        }
        __threadfence();       // release all this block's h stores
        __syncthreads();
        if (tid == 0) g_flags[bg * 32 + ug] = t + 1;
    }
}

// ============================================================
// Kernel C: out_loss (unchanged)
// ============================================================
__global__ void __launch_bounds__(256) out_loss(
    const float* __restrict__ Wd, const float* __restrict__ bd,
    const float* __restrict__ Y)
{
    __shared__ float h_s[512 * 20];
    __shared__ float red[8];
    int tid = threadIdx.x;
    int row0 = blockIdx.x * 16;

    #pragma unroll
    for (int i = 0; i < 32; i++) {
        int idx = tid + i * 256;
        int r = idx >> 9, k = idx & 511;
        h_s[k * 20 + r] = g_hs[(size_t)(row0 + r) * H_ + k];
    }
    __syncthreads();

    int cc = tid & 127;
    int rh = tid >> 7;
    ull acc2[4] = {};
    #pragma unroll 4
    for (int k = 0; k < 512; k++) {
        float w = Wd[(size_t)k * N_ + cc];
        ull wd; PACK2(wd, w, w);
        ulonglong2 ha = *(const ulonglong2*)&h_s[k * 20 + rh * 8];
        ulonglong2 hb = *(const ulonglong2*)&h_s[k * 20 + rh * 8 + 4];
        FMA2(acc2[0], ha.x, wd, acc2[0]);
        FMA2(acc2[1], ha.y, wd, acc2[1]);
        FMA2(acc2[2], hb.x, wd, acc2[2]);
        FMA2(acc2[3], hb.y, wd, acc2[3]);
    }
    float accv[8];
    #pragma unroll
    for (int p = 0; p < 4; p++) UNPACK2(accv[2 * p], accv[2 * p + 1], acc2[p]);

    float bdc = bd[cc];
    float lsum = 0.0f;
    #pragma unroll
    for (int i = 0; i < 8; i++) {
        int row = row0 + rh * 8 + i;
        float logit = 1.0f / (1.0f + expf(-(accv[i] + bdc)));
        float d = Y[(size_t)row * N_ + cc] - logit;
        lsum += d * d;
    }
    #pragma unroll
    for (int o = 16; o; o >>= 1) lsum += __shfl_xor_sync(0xFFFFFFFFu, lsum, o);
    if ((tid & 31) == 0) red[tid >> 5] = lsum;
    __syncthreads();
    if (tid == 0) {
        float ssum = 0.0f;
        #pragma unroll
        for (int i = 0; i < 8; i++) ssum += red[i];
        g_lpart[blockIdx.x] = ssum;
    }
}

// ============================================================
__global__ void finalize(float* __restrict__ out)
{
    __shared__ float red[8];
    int tid = threadIdx.x;
    float sv = 0.0f;
    for (int i = tid; i < 2048; i += 256) sv += g_lpart[i];
    #pragma unroll
    for (int o = 16; o; o >>= 1) sv += __shfl_xor_sync(0xFFFFFFFFu, sv, o);
    if ((tid & 31) == 0) red[tid >> 5] = sv;
    __syncthreads();
    if (tid == 0) {
        float tt = 0.0f;
        #pragma unroll
        for (int i = 0; i < 8; i++) tt += red[i];
        out[0] = tt * (100.0f / ((float)B_ * (float)T_ * (float)N_));
    }
}

// ============================================================
extern "C" void kernel_launch(void* const* d_in, const int* in_sizes, int n_in,
                              void* d_out, int out_size)
{
    const float* X  = (const float*)d_in[0];
    const float* Y  = (const float*)d_in[1];
    const float* Wx = (const float*)d_in[2];
    const float* Wh = (const float*)d_in[3];
    const float* b  = (const float*)d_in[4];
    const float* Wd = (const float*)d_in[5];
    const float* bd = (const float*)d_in[6];
    (void)in_sizes; (void)n_in; (void)out_size;

    cudaFuncSetAttribute(lstm_scan, cudaFuncAttributeMaxDynamicSharedMemorySize, SMEM_SCAN);

    dim3 gA(G_ / 64, BT_ / 64);
    xg_gemm<<<gA, 256>>>(X, Wx, b);             // also resets g_flags
    lstm_scan<<<NBLK, 256, SMEM_SCAN>>>(Wh);
    out_loss<<<BT_ / 16, 256>>>(Wd, bd, Y);
    finalize<<<1, 256>>>((float*)d_out);
}